// round 14
// baseline (speedup 1.0000x reference)
#include <cuda_runtime.h>
#include <cuda_fp16.h>
#include <cstdint>

#define BATCH 64
#define SEQ   512
#define ISZ   512
#define HSZ   1024
#define G4    4096
#define NCTA  128

// ---------- static device scratch ----------
__device__ __align__(16) __half g_x16[(size_t)BATCH * SEQ * ISZ];   // 32 MB
__device__ __align__(16) __half g_Wx16[(size_t)G4 * ISZ];           // 4 MB  [col][k]
__device__ __align__(16) __half g_Wh16[(size_t)NCTA * 32 * HSZ];    // 8 MB  [cta][c][k]
__device__ float  g_bias[G4];
__device__ __align__(16) __half g_gx16[(size_t)SEQ * NCTA * BATCH * 32]; // 268 MB [t][cta][b][32]
__device__ __align__(16) __half g_h[2][BATCH * HSZ];
__device__ __align__(16) float  g_hT[BATCH * HSZ];
__device__ unsigned g_flag[NCTA];

// ---------- asm helpers ----------
__device__ __forceinline__ void mma16816(float d[4],
    uint32_t a0, uint32_t a1, uint32_t a2, uint32_t a3, uint32_t b0, uint32_t b1) {
  asm volatile(
    "mma.sync.aligned.m16n8k16.row.col.f32.f16.f16.f32 "
    "{%0,%1,%2,%3}, {%4,%5,%6,%7}, {%8,%9}, {%0,%1,%2,%3};\n"
    : "+f"(d[0]), "+f"(d[1]), "+f"(d[2]), "+f"(d[3])
    : "r"(a0), "r"(a1), "r"(a2), "r"(a3), "r"(b0), "r"(b1));
}
__device__ __forceinline__ void ldsm4(uint32_t& r0, uint32_t& r1, uint32_t& r2,
                                      uint32_t& r3, uint32_t addr) {
  asm volatile("ldmatrix.sync.aligned.m8n8.x4.shared.b16 {%0,%1,%2,%3}, [%4];"
    : "=r"(r0), "=r"(r1), "=r"(r2), "=r"(r3) : "r"(addr));
}
__device__ __forceinline__ void cp16(uint32_t smem, const void* g) {
  asm volatile("cp.async.cg.shared.global [%0], [%1], 16;" :: "r"(smem), "l"(g));
}
__device__ __forceinline__ void cp_commit() { asm volatile("cp.async.commit_group;"); }
template <int N> __device__ __forceinline__ void cp_wait() {
  asm volatile("cp.async.wait_group %0;" :: "n"(N));
}
__device__ __forceinline__ unsigned ld_acq(const unsigned* p) {
  unsigned v;
  asm volatile("ld.acquire.gpu.global.u32 %0, [%1];" : "=r"(v) : "l"(p));
  return v;
}
__device__ __forceinline__ void st_rel(unsigned* p, unsigned v) {
  asm volatile("st.release.gpu.global.u32 [%0], %1;" :: "l"(p), "r"(v));
}
// fast sigmoid / tanh via MUFU ex2 (__expf max err ~2 ulp)
__device__ __forceinline__ float fsig(float x) {
  x = fminf(fmaxf(x, -30.f), 30.f);
  return __fdividef(1.f, 1.f + __expf(-x));
}
__device__ __forceinline__ float ftanh(float x) {
  x = fminf(fmaxf(x, -15.f), 15.f);
  float e = __expf(2.f * x);
  return __fdividef(e - 1.f, e + 1.f);
}

// ---------- init ----------
__global__ void k_init() {
  int i = blockIdx.x * blockDim.x + threadIdx.x;
  for (int idx = i; idx < BATCH * HSZ; idx += gridDim.x * blockDim.x)
    g_h[0][idx] = __float2half(0.f);
  if (i < NCTA) g_flag[i] = 0u;
}

// ---------- weight prep + x->fp16 (merged) ----------
__global__ void k_prep(const float* __restrict__ x,
                       const float* __restrict__ Wf, const float* __restrict__ Wfb,
                       const float* __restrict__ Wi, const float* __restrict__ Wib,
                       const float* __restrict__ Wo, const float* __restrict__ Wob,
                       const float* __restrict__ Wc, const float* __restrict__ Wcb) {
  const int gstr = gridDim.x * blockDim.x;
  const int gidx = blockIdx.x * blockDim.x + threadIdx.x;

  int total = G4 * 1536;
  for (int idx = gidx; idx < total; idx += gstr) {
    int col = idx / 1536, k = idx - (idx / 1536) * 1536;
    int gate = col >> 10, j = col & 1023;
    const float* Ws = (gate == 0) ? Wf : (gate == 1) ? Wi : (gate == 2) ? Wo : Wc;
    float v = Ws[(size_t)j * 1536 + k];
    if (k < ISZ) {
      g_Wx16[(size_t)col * ISZ + k] = __float2half(v);
    } else {
      int ct = j >> 3, u = j & 7, c = gate * 8 + u;
      g_Wh16[((size_t)ct * 32 + c) * HSZ + (k - ISZ)] = __float2half(v);
    }
    if (k == 0) {
      const float* Bs = (gate == 0) ? Wfb : (gate == 1) ? Wib : (gate == 2) ? Wob : Wcb;
      g_bias[col] = Bs[j];
    }
  }

  size_t total4 = (size_t)BATCH * SEQ * ISZ / 4;
  for (size_t i = gidx; i < total4; i += (size_t)gstr) {
    float4 v = *(const float4*)(x + i * 4);
    __half2* dst = (__half2*)(g_x16 + i * 4);
    dst[0] = __floats2half2_rn(v.x, v.y);
    dst[1] = __floats2half2_rn(v.z, v.w);
  }
}

// ---------- gx = x @ Wx^T + b : pipelined, 2 CTAs/SM, fp16 output ----------
#define GXC 136
#define GX_STAGEH ((64 + 128) * GXC)
#define GX_SMEM (2 * GX_STAGEH * 2)
__global__ void __launch_bounds__(256, 2) k_gemmx() {
  extern __shared__ __half sm[];
  const int t = blockIdx.y, col0 = blockIdx.x * 128, tid = threadIdx.x;
  const int lane = tid & 31, w = tid >> 5, gid = lane >> 2, tig = lane & 3;
  const int rb = 32 * (w & 1), cb = 32 * (w >> 1);

  auto issue = [&](int c, int s) {
    __half* As = sm + s * GX_STAGEH;
    __half* Bs = As + 64 * GXC;
    #pragma unroll
    for (int it = 0; it < 4; ++it) {
      int u = it * 256 + tid, b = u >> 4, ko = (u & 15) * 8;
      cp16((uint32_t)__cvta_generic_to_shared(As + b * GXC + ko),
           g_x16 + ((size_t)b * SEQ + t) * ISZ + c * 128 + ko);
    }
    #pragma unroll
    for (int it = 0; it < 8; ++it) {
      int u = it * 256 + tid, cc = u >> 4, ko = (u & 15) * 8;
      cp16((uint32_t)__cvta_generic_to_shared(Bs + cc * GXC + ko),
           g_Wx16 + (size_t)(col0 + cc) * ISZ + c * 128 + ko);
    }
    cp_commit();
  };

  uint32_t a_ad[2], b_ad[2];
  {
    int row16 = lane & 15, koff = (lane >> 4) * 8;
    a_ad[0] = (uint32_t)__cvta_generic_to_shared(sm + (rb + row16) * GXC + koff);
    a_ad[1] = (uint32_t)__cvta_generic_to_shared(sm + (rb + 16 + row16) * GXC + koff);
    int j = lane >> 3, r = lane & 7;
    b_ad[0] = (uint32_t)__cvta_generic_to_shared(
        sm + 64 * GXC + (cb + (j >> 1) * 8 + r) * GXC + (j & 1) * 8);
    b_ad[1] = (uint32_t)__cvta_generic_to_shared(
        sm + 64 * GXC + (cb + 16 + (j >> 1) * 8 + r) * GXC + (j & 1) * 8);
  }

  float acc[2][4][4];
  #pragma unroll
  for (int m = 0; m < 2; m++)
    #pragma unroll
    for (int n = 0; n < 4; n++)
      #pragma unroll
      for (int q = 0; q < 4; q++) acc[m][n][q] = 0.f;

  issue(0, 0);
  #pragma unroll
  for (int c = 0; c < 4; ++c) {
    if (c < 3) { issue(c + 1, (c + 1) & 1); cp_wait<1>(); }
    else       { cp_wait<0>(); }
    __syncthreads();
    uint32_t so = (uint32_t)((c & 1) * GX_STAGEH * 2);
    #pragma unroll
    for (int kk = 0; kk < 8; ++kk) {
      uint32_t kb = so + kk * 32;
      uint32_t a[2][4], b[4][2];
      ldsm4(a[0][0], a[0][1], a[0][2], a[0][3], a_ad[0] + kb);
      ldsm4(a[1][0], a[1][1], a[1][2], a[1][3], a_ad[1] + kb);
      ldsm4(b[0][0], b[0][1], b[1][0], b[1][1], b_ad[0] + kb);
      ldsm4(b[2][0], b[2][1], b[3][0], b[3][1], b_ad[1] + kb);
      #pragma unroll
      for (int m = 0; m < 2; m++)
        #pragma unroll
        for (int n = 0; n < 4; n++)
          mma16816(acc[m][n], a[m][0], a[m][1], a[m][2], a[m][3], b[n][0], b[n][1]);
    }
    __syncthreads();
  }

  #pragma unroll
  for (int m = 0; m < 2; m++) {
    #pragma unroll
    for (int n = 0; n < 4; n++) {
      int row = rb + m * 16 + gid;
      int gcol = col0 + cb + n * 8 + tig * 2;
      int gate = gcol >> 10, j = gcol & 1023, ct = j >> 3, u = j & 7;
      int c = gate * 8 + u;
      float b0 = g_bias[gcol], b1 = g_bias[gcol + 1];
      size_t base = ((size_t)t * NCTA + ct) * (BATCH * 32);
      *(__half2*)(g_gx16 + base + (size_t)row * 32 + c) =
          __floats2half2_rn(acc[m][n][0] + b0, acc[m][n][1] + b1);
      *(__half2*)(g_gx16 + base + (size_t)(row + 8) * 32 + c) =
          __floats2half2_rn(acc[m][n][2] + b0, acc[m][n][3] + b1);
    }
  }
}

// ---------- persistent recurrence: 128 CTAs x 256 threads ----------
// New tiling: warp w -> K-half ks=w&1, m-block mb=(w>>1)&1 (32 rows), n-half
// nh=w>>2 (16 cols). 3 LDSM feed 4 MMA (was 2:2) -> SMEM reads 512->384KB/step.
// Each K-group (128 thr) stages its own K-half (2 cp.async groups) and syncs
// with a named 128-thread barrier; K-halves merged by a pairwise SMEM reduction.
#define LSTM_SMEM (64*1032*2 + 32*1032*2 + 64*33*4 + 512*4 + 4*544*4)
__global__ void __launch_bounds__(256, 1) k_lstm() {
  extern __shared__ char smraw[];
  __half* h_sm  = (__half*)smraw;                            // [64][1032]
  __half* w_sm  = (__half*)(smraw + 64 * 1032 * 2);          // [32][1032]
  float*  gates = (float*)(smraw + (64 + 32) * 1032 * 2);    // [64][33]
  float*  c_sm  = gates + 64 * 33;                           // [8][64] u*64+b
  float*  red   = c_sm + 512;                                // [4][544]

  const int tid = threadIdx.x, cta = blockIdx.x;
  const int lane = tid & 31, w = tid >> 5;
  const int gid = lane >> 2, tig = lane & 3;
  const int ks = w & 1, mb = (w >> 1) & 1, nh = w >> 2, n0 = nh * 16;
  const int pid = w >> 1;                       // warp-pair id (w, w^1)
  const int gt = (w >> 1) * 32 + lane;          // thread idx within K-group

  // persistent Wh slice: 32 x 1024 halfs (64 KB)
  {
    const uint4* src = (const uint4*)(g_Wh16 + (size_t)cta * 32 * HSZ);
    #pragma unroll
    for (int it = 0; it < 16; ++it) {
      int i8 = (tid + it * 256) * 8, r = i8 >> 10, k = i8 & 1023;
      *(uint4*)(w_sm + r * 1032 + k) = src[tid + it * 256];
    }
  }
  for (int i = tid; i < 512; i += 256) c_sm[i] = 0.f;
  __syncthreads();

  // ldmatrix base addresses (K-half baked in)
  uint32_t a_ad[2], b_ad;
  {
    int row16 = lane & 15, koff = (lane >> 4) * 8;
    a_ad[0] = (uint32_t)__cvta_generic_to_shared(
        h_sm + (mb * 32 + row16) * 1032 + koff + ks * 512);
    a_ad[1] = (uint32_t)__cvta_generic_to_shared(
        h_sm + (mb * 32 + 16 + row16) * 1032 + koff + ks * 512);
    int j = lane >> 3, r = lane & 7;
    b_ad = (uint32_t)__cvta_generic_to_shared(
        w_sm + (n0 + (j >> 1) * 8 + r) * 1032 + (j & 1) * 8 + ks * 512);
  }

  const int pb = tid & 63, pu = (tid >> 6) * 2;   // pointwise (batch, unit-pair)

  for (int t = 0; t < SEQ; ++t) {
    int p = t & 1;

    // prefetch gx for this step (fp16; independent of the barrier)
    const __half* gxp = g_gx16 + ((size_t)t * NCTA + cta) * (BATCH * 32) + pb * 32 + pu;
    float2 gf = __half22float2(*(const __half2*)(gxp + 0));
    float2 gi = __half22float2(*(const __half2*)(gxp + 8));
    float2 go = __half22float2(*(const __half2*)(gxp + 16));
    float2 gg = __half22float2(*(const __half2*)(gxp + 24));

    // wait for every CTA to finish step t-1 (acquire)
    if (t > 0) {
      if (tid < NCTA) {
        while (ld_acq(&g_flag[tid]) < (unsigned)t) { }
      }
      __syncthreads();
    }

    // stage own K-half: 2 chunks of 256 halfs/row, group-local cp groups
    const char* hsrc = (const char*)g_h[p];
    #pragma unroll
    for (int cc = 0; cc < 2; ++cc) {
      #pragma unroll
      for (int it = 0; it < 16; ++it) {
        int i = it * 128 + gt;                 // 2048 x 16B units per chunk
        int b = i >> 5, un = i & 31;
        int off = ks * 512 + cc * 256 + un * 8;   // halfs within row
        uint32_t dst = (uint32_t)__cvta_generic_to_shared(h_sm + b * 1032 + off);
        cp16(dst, hsrc + ((size_t)b * 1024 + off) * 2);
      }
      cp_commit();
    }

    float acc[2][2][4];
    #pragma unroll
    for (int a = 0; a < 2; a++)
      #pragma unroll
      for (int n = 0; n < 2; n++)
        #pragma unroll
        for (int q = 0; q < 4; q++) acc[a][n][q] = 0.f;

    #pragma unroll
    for (int cc = 0; cc < 2; ++cc) {
      if (cc == 0) cp_wait<1>(); else cp_wait<0>();
      asm volatile("bar.sync %0, 128;" :: "r"(1 + ks) : "memory");
      #pragma unroll
      for (int kk = 0; kk < 16; ++kk) {
        uint32_t kb = (uint32_t)((cc * 256 + kk * 16) * 2);
        uint32_t a0, a1, a2, a3, c0, c1, c2, c3, b00, b01, b10, b11;
        ldsm4(a0, a1, a2, a3, a_ad[0] + kb);
        ldsm4(c0, c1, c2, c3, a_ad[1] + kb);
        ldsm4(b00, b01, b10, b11, b_ad + kb);
        mma16816(acc[0][0], a0, a1, a2, a3, b00, b01);
        mma16816(acc[0][1], a0, a1, a2, a3, b10, b11);
        mma16816(acc[1][0], c0, c1, c2, c3, b00, b01);
        mma16816(acc[1][1], c0, c1, c2, c3, b10, b11);
      }
    }

    // K-half reduction: odd (ks=1) warps publish, even warps merge + write gates
    if (ks) {
      float* rp = red + pid * 544 + lane * 17;
      #pragma unroll
      for (int a = 0; a < 2; a++)
        #pragma unroll
        for (int n = 0; n < 2; n++)
          #pragma unroll
          for (int q = 0; q < 4; q++) rp[a * 8 + n * 4 + q] = acc[a][n][q];
    }
    __syncthreads();
    if (!ks) {
      const float* rp = red + pid * 544 + lane * 17;
      #pragma unroll
      for (int a = 0; a < 2; a++) {
        #pragma unroll
        for (int n = 0; n < 2; n++) {
          #pragma unroll
          for (int q = 0; q < 4; q++) acc[a][n][q] += rp[a * 8 + n * 4 + q];
          int r0 = mb * 32 + a * 16 + gid;
          int cb = n0 + n * 8 + 2 * tig;
          gates[r0 * 33 + cb]           = acc[a][n][0];
          gates[r0 * 33 + cb + 1]       = acc[a][n][1];
          gates[(r0 + 8) * 33 + cb]     = acc[a][n][2];
          gates[(r0 + 8) * 33 + cb + 1] = acc[a][n][3];
        }
      }
    }
    __syncthreads();

    // fused pointwise LSTM update: thread handles (pb, pu) and (pb, pu+1)
    float hv[2];
    #pragma unroll
    for (int q = 0; q < 2; ++q) {
      int u = pu + q;
      float fg = fsig(gates[pb * 33 + u]       + (q ? gf.y : gf.x));
      float ig = fsig(gates[pb * 33 + 8 + u]   + (q ? gi.y : gi.x));
      float og = fsig(gates[pb * 33 + 16 + u]  + (q ? go.y : go.x));
      float cg = ftanh(gates[pb * 33 + 24 + u] + (q ? gg.y : gg.x));
      float cn = fg * c_sm[u * 64 + pb] + ig * cg;
      c_sm[u * 64 + pb] = cn;
      hv[q] = og * ftanh(cn);
    }
    *(__half2*)(g_h[p ^ 1] + pb * HSZ + cta * 8 + pu) = __floats2half2_rn(hv[0], hv[1]);
    if (t == SEQ - 1)
      *(float2*)(g_hT + pb * HSZ + cta * 8 + pu) = make_float2(hv[0], hv[1]);

    // publish (release); CTA barrier + release-store carry visibility
    __syncthreads();
    if (tid == 0) st_rel(&g_flag[cta], (unsigned)(t + 1));
  }
}

// ---------- logits ----------
__global__ void k_logits(const float* __restrict__ ow, const float* __restrict__ ob,
                         float* __restrict__ out) {
  int b = blockIdx.x, tid = threadIdx.x, o = tid >> 5, lane = tid & 31;
  if (o >= 10) return;
  float s = 0.f;
  for (int k = lane; k < HSZ; k += 32) s += g_hT[b * HSZ + k] * ow[o * HSZ + k];
  #pragma unroll
  for (int d = 16; d > 0; d >>= 1) s += __shfl_down_sync(0xFFFFFFFF, s, d);
  if (lane == 0) out[b * 10 + o] = s + ob[o];
}

// ---------- host ----------
extern "C" void kernel_launch(void* const* d_in, const int* in_sizes, int n_in,
                              void* d_out, int out_size) {
  const float* x   = (const float*)d_in[0];
  const float* Wf  = (const float*)d_in[1];  const float* Wfb = (const float*)d_in[2];
  const float* Wi  = (const float*)d_in[3];  const float* Wib = (const float*)d_in[4];
  const float* Wo  = (const float*)d_in[5];  const float* Wob = (const float*)d_in[6];
  const float* Wc  = (const float*)d_in[7];  const float* Wcb = (const float*)d_in[8];
  const float* ow  = (const float*)d_in[9];  const float* ob  = (const float*)d_in[10];
  float* out = (float*)d_out;

  cudaFuncSetAttribute(k_gemmx, cudaFuncAttributeMaxDynamicSharedMemorySize, GX_SMEM);
  cudaFuncSetAttribute(k_lstm,  cudaFuncAttributeMaxDynamicSharedMemorySize, LSTM_SMEM);

  k_init<<<256, 256>>>();
  k_prep<<<8192, 256>>>(x, Wf, Wfb, Wi, Wib, Wo, Wob, Wc, Wcb);
  k_gemmx<<<dim3(32, SEQ), 256, GX_SMEM>>>();
  k_lstm<<<NCTA, 256, LSTM_SMEM>>>();
  k_logits<<<BATCH, 320>>>(ow, ob, out);
}

// round 15
// speedup vs baseline: 1.6508x; 1.6508x over previous
#include <cuda_runtime.h>
#include <cuda_fp16.h>
#include <cstdint>

#define BATCH 64
#define SEQ   512
#define ISZ   512
#define HSZ   1024
#define G4    4096
#define NCTA  128

// ---------- static device scratch ----------
__device__ __align__(16) __half g_x16[(size_t)BATCH * SEQ * ISZ];   // 32 MB
__device__ __align__(16) __half g_Wx16[(size_t)G4 * ISZ];           // 4 MB  [col][k]
__device__ __align__(16) __half g_Wh16[(size_t)NCTA * 32 * HSZ];    // 8 MB  [cta][c][k]
__device__ float  g_bias[G4];
__device__ float  g_gx[(size_t)SEQ * NCTA * BATCH * 32];            // 536 MB [t][cta][b][32]
__device__ __align__(16) __half g_h[2][BATCH * HSZ];
__device__ __align__(16) float  g_hT[BATCH * HSZ];
__device__ unsigned g_flag[NCTA];

// ---------- asm helpers ----------
__device__ __forceinline__ void mma16816(float d[4],
    uint32_t a0, uint32_t a1, uint32_t a2, uint32_t a3, uint32_t b0, uint32_t b1) {
  asm volatile(
    "mma.sync.aligned.m16n8k16.row.col.f32.f16.f16.f32 "
    "{%0,%1,%2,%3}, {%4,%5,%6,%7}, {%8,%9}, {%0,%1,%2,%3};\n"
    : "+f"(d[0]), "+f"(d[1]), "+f"(d[2]), "+f"(d[3])
    : "r"(a0), "r"(a1), "r"(a2), "r"(a3), "r"(b0), "r"(b1));
}
__device__ __forceinline__ void ldsm4(uint32_t& r0, uint32_t& r1, uint32_t& r2,
                                      uint32_t& r3, uint32_t addr) {
  asm volatile("ldmatrix.sync.aligned.m8n8.x4.shared.b16 {%0,%1,%2,%3}, [%4];"
    : "=r"(r0), "=r"(r1), "=r"(r2), "=r"(r3) : "r"(addr));
}
__device__ __forceinline__ void cp16(uint32_t smem, const void* g) {
  asm volatile("cp.async.cg.shared.global [%0], [%1], 16;" :: "r"(smem), "l"(g));
}
__device__ __forceinline__ void cp_commit() { asm volatile("cp.async.commit_group;"); }
template <int N> __device__ __forceinline__ void cp_wait() {
  asm volatile("cp.async.wait_group %0;" :: "n"(N));
}
__device__ __forceinline__ unsigned ld_acq(const unsigned* p) {
  unsigned v;
  asm volatile("ld.acquire.gpu.global.u32 %0, [%1];" : "=r"(v) : "l"(p));
  return v;
}
__device__ __forceinline__ void st_rel(unsigned* p, unsigned v) {
  asm volatile("st.release.gpu.global.u32 [%0], %1;" :: "l"(p), "r"(v));
}
// fast sigmoid / tanh via MUFU ex2 (__expf max err ~2 ulp)
__device__ __forceinline__ float fsig(float x) {
  x = fminf(fmaxf(x, -30.f), 30.f);
  return __fdividef(1.f, 1.f + __expf(-x));
}
__device__ __forceinline__ float ftanh(float x) {
  x = fminf(fmaxf(x, -15.f), 15.f);
  float e = __expf(2.f * x);
  return __fdividef(e - 1.f, e + 1.f);
}

// ---------- init ----------
__global__ void k_init() {
  int i = blockIdx.x * blockDim.x + threadIdx.x;
  for (int idx = i; idx < BATCH * HSZ; idx += gridDim.x * blockDim.x)
    g_h[0][idx] = __float2half(0.f);
  if (i < NCTA) g_flag[i] = 0u;
}

// ---------- x -> fp16 ----------
__global__ void k_convx(const float* __restrict__ x) {
  size_t total4 = (size_t)BATCH * SEQ * ISZ / 4;
  for (size_t i = blockIdx.x * (size_t)blockDim.x + threadIdx.x; i < total4;
       i += (size_t)gridDim.x * blockDim.x) {
    float4 v = *(const float4*)(x + i * 4);
    __half2* dst = (__half2*)(g_x16 + i * 4);
    dst[0] = __floats2half2_rn(v.x, v.y);
    dst[1] = __floats2half2_rn(v.z, v.w);
  }
}

// ---------- weight prep ----------
__global__ void k_prep(const float* __restrict__ Wf, const float* __restrict__ Wfb,
                       const float* __restrict__ Wi, const float* __restrict__ Wib,
                       const float* __restrict__ Wo, const float* __restrict__ Wob,
                       const float* __restrict__ Wc, const float* __restrict__ Wcb) {
  int total = G4 * 1536;
  for (int idx = blockIdx.x * blockDim.x + threadIdx.x; idx < total;
       idx += gridDim.x * blockDim.x) {
    int col = idx / 1536, k = idx - (idx / 1536) * 1536;
    int gate = col >> 10, j = col & 1023;
    const float* Ws = (gate == 0) ? Wf : (gate == 1) ? Wi : (gate == 2) ? Wo : Wc;
    float v = Ws[(size_t)j * 1536 + k];
    if (k < ISZ) {
      g_Wx16[(size_t)col * ISZ + k] = __float2half(v);
    } else {
      int ct = j >> 3, u = j & 7, c = gate * 8 + u;
      g_Wh16[((size_t)ct * 32 + c) * HSZ + (k - ISZ)] = __float2half(v);
    }
    if (k == 0) {
      const float* Bs = (gate == 0) ? Wfb : (gate == 1) ? Wib : (gate == 2) ? Wob : Wcb;
      g_bias[col] = Bs[j];
    }
  }
}

// ---------- gx = x @ Wx^T + b : pipelined, 2 CTAs/SM, f32 output ----------
#define GXC 136
#define GX_STAGEH ((64 + 128) * GXC)           // halfs per stage
#define GX_SMEM (2 * GX_STAGEH * 2)            // 104448 bytes
__global__ void __launch_bounds__(256, 2) k_gemmx() {
  extern __shared__ __half sm[];
  const int t = blockIdx.y, col0 = blockIdx.x * 128, tid = threadIdx.x;
  const int lane = tid & 31, w = tid >> 5, gid = lane >> 2, tig = lane & 3;
  const int rb = 32 * (w & 1), cb = 32 * (w >> 1);

  // stage one 128-wide K-chunk: each row = 128 halfs = 16 x 16B units
  auto issue = [&](int c, int s) {
    __half* As = sm + s * GX_STAGEH;
    __half* Bs = As + 64 * GXC;
    #pragma unroll
    for (int it = 0; it < 4; ++it) {                 // 64 rows * 16 = 1024 units
      int u = it * 256 + tid, b = u >> 4, ko = (u & 15) * 8;
      cp16((uint32_t)__cvta_generic_to_shared(As + b * GXC + ko),
           g_x16 + ((size_t)b * SEQ + t) * ISZ + c * 128 + ko);
    }
    #pragma unroll
    for (int it = 0; it < 8; ++it) {                 // 128 rows * 16 = 2048 units
      int u = it * 256 + tid, cc = u >> 4, ko = (u & 15) * 8;
      cp16((uint32_t)__cvta_generic_to_shared(Bs + cc * GXC + ko),
           g_Wx16 + (size_t)(col0 + cc) * ISZ + c * 128 + ko);
    }
    cp_commit();
  };

  uint32_t a_ad[2], b_ad[2];
  {
    int row16 = lane & 15, koff = (lane >> 4) * 8;
    a_ad[0] = (uint32_t)__cvta_generic_to_shared(sm + (rb + row16) * GXC + koff);
    a_ad[1] = (uint32_t)__cvta_generic_to_shared(sm + (rb + 16 + row16) * GXC + koff);
    int j = lane >> 3, r = lane & 7;
    b_ad[0] = (uint32_t)__cvta_generic_to_shared(
        sm + 64 * GXC + (cb + (j >> 1) * 8 + r) * GXC + (j & 1) * 8);
    b_ad[1] = (uint32_t)__cvta_generic_to_shared(
        sm + 64 * GXC + (cb + 16 + (j >> 1) * 8 + r) * GXC + (j & 1) * 8);
  }

  float acc[2][4][4];
  #pragma unroll
  for (int m = 0; m < 2; m++)
    #pragma unroll
    for (int n = 0; n < 4; n++)
      #pragma unroll
      for (int q = 0; q < 4; q++) acc[m][n][q] = 0.f;

  issue(0, 0);
  #pragma unroll
  for (int c = 0; c < 4; ++c) {
    if (c < 3) { issue(c + 1, (c + 1) & 1); cp_wait<1>(); }
    else       { cp_wait<0>(); }
    __syncthreads();
    uint32_t so = (uint32_t)((c & 1) * GX_STAGEH * 2);  // stage byte offset
    #pragma unroll
    for (int kk = 0; kk < 8; ++kk) {
      uint32_t kb = so + kk * 32;
      uint32_t a[2][4], b[4][2];
      ldsm4(a[0][0], a[0][1], a[0][2], a[0][3], a_ad[0] + kb);
      ldsm4(a[1][0], a[1][1], a[1][2], a[1][3], a_ad[1] + kb);
      ldsm4(b[0][0], b[0][1], b[1][0], b[1][1], b_ad[0] + kb);
      ldsm4(b[2][0], b[2][1], b[3][0], b[3][1], b_ad[1] + kb);
      #pragma unroll
      for (int m = 0; m < 2; m++)
        #pragma unroll
        for (int n = 0; n < 4; n++)
          mma16816(acc[m][n], a[m][0], a[m][1], a[m][2], a[m][3], b[n][0], b[n][1]);
    }
    __syncthreads();
  }

  // epilogue: + bias, f32, layout [t][ct][row][32] with plain gate order
  #pragma unroll
  for (int m = 0; m < 2; m++) {
    #pragma unroll
    for (int n = 0; n < 4; n++) {
      int row = rb + m * 16 + gid;
      int gcol = col0 + cb + n * 8 + tig * 2;
      int gate = gcol >> 10, j = gcol & 1023, ct = j >> 3, u = j & 7;
      int c = gate * 8 + u;
      float b0 = g_bias[gcol], b1 = g_bias[gcol + 1];
      size_t base = ((size_t)t * NCTA + ct) * (BATCH * 32);
      float* o0 = g_gx + base + (size_t)row * 32 + c;
      o0[0] = acc[m][n][0] + b0;  o0[1] = acc[m][n][1] + b1;
      float* o1 = g_gx + base + (size_t)(row + 8) * 32 + c;
      o1[0] = acc[m][n][2] + b0;  o1[1] = acc[m][n][3] + b1;
    }
  }
}

// ---------- persistent recurrence: 128 CTAs x 256 threads (R5 structure) ----------
#define LSTM_SMEM (64 * 1032 * 2 + 32 * 1032 * 2 + 64 * 33 * 4 + 512 * 4)
__global__ void __launch_bounds__(256, 1) k_lstm() {
  extern __shared__ char smraw[];
  __half* h_sm  = (__half*)smraw;                            // [64][1032]
  __half* w_sm  = (__half*)(smraw + 64 * 1032 * 2);          // [32][1032]
  float*  gates = (float*)(smraw + (64 + 32) * 1032 * 2);    // [64][33]
  float*  c_sm  = gates + 64 * 33;                           // [8][64] u*64+b

  const int tid = threadIdx.x, cta = blockIdx.x;
  const int lane = tid & 31, w = tid >> 5;
  const int gid = lane >> 2, tig = lane & 3;
  const int mblk = w & 3, n0 = (w >> 2) * 16;

  // persistent Wh slice: 32 x 1024 halfs (64 KB)
  {
    const uint4* src = (const uint4*)(g_Wh16 + (size_t)cta * 32 * HSZ);
    #pragma unroll
    for (int it = 0; it < 16; ++it) {
      int i8 = (tid + it * 256) * 8, r = i8 >> 10, k = i8 & 1023;
      *(uint4*)(w_sm + r * 1032 + k) = src[tid + it * 256];
    }
  }
  for (int i = tid; i < 512; i += 256) c_sm[i] = 0.f;
  __syncthreads();

  // ldmatrix base addresses
  uint32_t a_ad, b_ad;
  {
    int row16 = lane & 15, koff = (lane >> 4) * 8;
    a_ad = (uint32_t)__cvta_generic_to_shared(h_sm + (mblk * 16 + row16) * 1032 + koff);
    int j = lane >> 3, r = lane & 7;
    b_ad = (uint32_t)__cvta_generic_to_shared(
        w_sm + (n0 + (j >> 1) * 8 + r) * 1032 + (j & 1) * 8);
  }

  const int pb = tid & 63, pu = (tid >> 6) * 2;   // pointwise (batch, unit-pair)

  for (int t = 0; t < SEQ; ++t) {
    int p = t & 1;

    // prefetch gx for this step (independent of the barrier)
    const float* gxp = g_gx + ((size_t)t * NCTA + cta) * (BATCH * 32) + pb * 32 + pu;
    float2 gf = *(const float2*)(gxp + 0);
    float2 gi = *(const float2*)(gxp + 8);
    float2 go = *(const float2*)(gxp + 16);
    float2 gg = *(const float2*)(gxp + 24);

    // wait for every CTA to finish step t-1 (acquire)
    if (t > 0) {
      if (tid < NCTA) {
        while (ld_acq(&g_flag[tid]) < (unsigned)t) { }
      }
      __syncthreads();
    }

    // stage h via cp.async.cg in 4 K-chunks of 256 (overlaps with MMA below)
    const char* hsrc = (const char*)g_h[p];
    #pragma unroll
    for (int c = 0; c < 4; ++c) {
      #pragma unroll
      for (int it = 0; it < 8; ++it) {
        int i = it * 256 + tid;                  // 2048 x 16B units per chunk
        int b = i >> 5, koff = (i & 31) * 8;
        uint32_t dst = (uint32_t)__cvta_generic_to_shared(
            h_sm + b * 1032 + c * 256 + koff);
        cp16(dst, hsrc + (size_t)(b * 1024 + c * 256 + koff) * 2);
      }
      cp_commit();
    }

    float acc[2][4];
    #pragma unroll
    for (int n = 0; n < 2; n++)
      #pragma unroll
      for (int q = 0; q < 4; q++) acc[n][q] = 0.f;

    #pragma unroll
    for (int c = 0; c < 4; ++c) {
      if (c == 0) cp_wait<3>();
      else if (c == 1) cp_wait<2>();
      else if (c == 2) cp_wait<1>();
      else cp_wait<0>();
      __syncthreads();
      #pragma unroll
      for (int kk = 0; kk < 16; ++kk) {
        uint32_t kb = (uint32_t)(c * 512 + kk * 32);
        uint32_t a0, a1, a2, a3, b00, b01, b10, b11;
        ldsm4(a0, a1, a2, a3, a_ad + kb);
        ldsm4(b00, b01, b10, b11, b_ad + kb);
        mma16816(acc[0], a0, a1, a2, a3, b00, b01);
        mma16816(acc[1], a0, a1, a2, a3, b10, b11);
      }
    }

    // exchange gate partials via SMEM (each warp owns 16 of the 32 cols)
    #pragma unroll
    for (int hh = 0; hh < 2; ++hh) {
      int r = mblk * 16 + gid + hh * 8;
      gates[r * 33 + n0 + 2 * tig]         = acc[0][hh * 2 + 0];
      gates[r * 33 + n0 + 2 * tig + 1]     = acc[0][hh * 2 + 1];
      gates[r * 33 + n0 + 8 + 2 * tig]     = acc[1][hh * 2 + 0];
      gates[r * 33 + n0 + 8 + 2 * tig + 1] = acc[1][hh * 2 + 1];
    }
    __syncthreads();

    // fused pointwise LSTM update: thread handles (pb, pu) and (pb, pu+1)
    float hv[2];
    #pragma unroll
    for (int q = 0; q < 2; ++q) {
      int u = pu + q;
      float fg = fsig(gates[pb * 33 + u]       + (q ? gf.y : gf.x));
      float ig = fsig(gates[pb * 33 + 8 + u]   + (q ? gi.y : gi.x));
      float og = fsig(gates[pb * 33 + 16 + u]  + (q ? go.y : go.x));
      float cg = ftanh(gates[pb * 33 + 24 + u] + (q ? gg.y : gg.x));
      float cn = fg * c_sm[u * 64 + pb] + ig * cg;
      c_sm[u * 64 + pb] = cn;
      hv[q] = og * ftanh(cn);
    }
    *(__half2*)(g_h[p ^ 1] + pb * HSZ + cta * 8 + pu) = __floats2half2_rn(hv[0], hv[1]);
    if (t == SEQ - 1)
      *(float2*)(g_hT + pb * HSZ + cta * 8 + pu) = make_float2(hv[0], hv[1]);

    // publish (release); CTA barrier + release-store carry visibility
    __syncthreads();
    if (tid == 0) st_rel(&g_flag[cta], (unsigned)(t + 1));
  }
}

// ---------- logits ----------
__global__ void k_logits(const float* __restrict__ ow, const float* __restrict__ ob,
                         float* __restrict__ out) {
  int b = blockIdx.x, tid = threadIdx.x, o = tid >> 5, lane = tid & 31;
  if (o >= 10) return;
  float s = 0.f;
  for (int k = lane; k < HSZ; k += 32) s += g_hT[b * HSZ + k] * ow[o * HSZ + k];
  #pragma unroll
  for (int d = 16; d > 0; d >>= 1) s += __shfl_down_sync(0xFFFFFFFF, s, d);
  if (lane == 0) out[b * 10 + o] = s + ob[o];
}

// ---------- host ----------
extern "C" void kernel_launch(void* const* d_in, const int* in_sizes, int n_in,
                              void* d_out, int out_size) {
  const float* x   = (const float*)d_in[0];
  const float* Wf  = (const float*)d_in[1];  const float* Wfb = (const float*)d_in[2];
  const float* Wi  = (const float*)d_in[3];  const float* Wib = (const float*)d_in[4];
  const float* Wo  = (const float*)d_in[5];  const float* Wob = (const float*)d_in[6];
  const float* Wc  = (const float*)d_in[7];  const float* Wcb = (const float*)d_in[8];
  const float* ow  = (const float*)d_in[9];  const float* ob  = (const float*)d_in[10];
  float* out = (float*)d_out;

  cudaFuncSetAttribute(k_gemmx, cudaFuncAttributeMaxDynamicSharedMemorySize, GX_SMEM);
  cudaFuncSetAttribute(k_lstm,  cudaFuncAttributeMaxDynamicSharedMemorySize, LSTM_SMEM);

  k_init<<<256, 256>>>();
  k_convx<<<4096, 256>>>(x);
  k_prep<<<8192, 256>>>(Wf, Wfb, Wi, Wib, Wo, Wob, Wc, Wcb);
  k_gemmx<<<dim3(32, SEQ), 256, GX_SMEM>>>();
  k_lstm<<<NCTA, 256, LSTM_SMEM>>>();
  k_logits<<<BATCH, 320>>>(ow, ob, out);
}

// round 17
// speedup vs baseline: 1.7423x; 1.0554x over previous
#include <cuda_runtime.h>
#include <cuda.h>
#include <cuda_fp16.h>
#include <cstdint>

#define BATCH 64
#define SEQ   512
#define ISZ   512
#define HSZ   1024
#define G4    4096
#define NCTA  128

// ---------- static device scratch ----------
__device__ __align__(16) __half g_x16[(size_t)BATCH * SEQ * ISZ];   // 32 MB
__device__ __align__(16) __half g_Wx16[(size_t)G4 * ISZ];           // 4 MB  [col][k]
__device__ __align__(16) __half g_Wh16[(size_t)NCTA * 32 * HSZ];    // 8 MB  [cta][c][k]
__device__ float  g_bias[G4];
__device__ float  g_gx[(size_t)SEQ * NCTA * BATCH * 32];            // 536 MB [t][cta][b][32]
// h double buffer, TMA layout: [kc(16)][b(64)][64 halfs] per buffer
__device__ __align__(1024) __half g_hbuf[2][16 * 64 * 64];
__device__ __align__(16) float  g_hT[BATCH * HSZ];
__device__ unsigned g_flag[NCTA];

// ---------- asm helpers ----------
__device__ __forceinline__ void mma16816(float d[4],
    uint32_t a0, uint32_t a1, uint32_t a2, uint32_t a3, uint32_t b0, uint32_t b1) {
  asm volatile(
    "mma.sync.aligned.m16n8k16.row.col.f32.f16.f16.f32 "
    "{%0,%1,%2,%3}, {%4,%5,%6,%7}, {%8,%9}, {%0,%1,%2,%3};\n"
    : "+f"(d[0]), "+f"(d[1]), "+f"(d[2]), "+f"(d[3])
    : "r"(a0), "r"(a1), "r"(a2), "r"(a3), "r"(b0), "r"(b1));
}
__device__ __forceinline__ void ldsm4(uint32_t& r0, uint32_t& r1, uint32_t& r2,
                                      uint32_t& r3, uint32_t addr) {
  asm volatile("ldmatrix.sync.aligned.m8n8.x4.shared.b16 {%0,%1,%2,%3}, [%4];"
    : "=r"(r0), "=r"(r1), "=r"(r2), "=r"(r3) : "r"(addr));
}
__device__ __forceinline__ void cp16(uint32_t smem, const void* g) {
  asm volatile("cp.async.cg.shared.global [%0], [%1], 16;" :: "r"(smem), "l"(g));
}
__device__ __forceinline__ void cp_commit() { asm volatile("cp.async.commit_group;"); }
template <int N> __device__ __forceinline__ void cp_wait() {
  asm volatile("cp.async.wait_group %0;" :: "n"(N));
}
__device__ __forceinline__ unsigned ld_acq(const unsigned* p) {
  unsigned v;
  asm volatile("ld.acquire.gpu.global.u32 %0, [%1];" : "=r"(v) : "l"(p));
  return v;
}
__device__ __forceinline__ void st_rel(unsigned* p, unsigned v) {
  asm volatile("st.release.gpu.global.u32 [%0], %1;" :: "l"(p), "r"(v));
}
__device__ __forceinline__ float fsig(float x) {
  x = fminf(fmaxf(x, -30.f), 30.f);
  return __fdividef(1.f, 1.f + __expf(-x));
}
__device__ __forceinline__ float ftanh(float x) {
  x = fminf(fmaxf(x, -15.f), 15.f);
  float e = __expf(2.f * x);
  return __fdividef(e - 1.f, e + 1.f);
}
__device__ __forceinline__ void mbar_wait(uint32_t mbar, uint32_t parity) {
  asm volatile(
    "{\n\t.reg .pred P;\n\t"
    "W%=:\n\t"
    "mbarrier.try_wait.parity.acquire.cta.shared::cta.b64 P, [%0], %1, 0x989680;\n\t"
    "@P bra D%=;\n\t"
    "bra W%=;\n\t"
    "D%=:\n\t}"
    :: "r"(mbar), "r"(parity) : "memory");
}

// ---------- init ----------
__global__ void k_init() {
  int i = blockIdx.x * blockDim.x + threadIdx.x;
  for (int idx = i; idx < 16 * 64 * 64; idx += gridDim.x * blockDim.x)
    g_hbuf[0][idx] = __float2half(0.f);
  if (i < NCTA) g_flag[i] = 0u;
}

// ---------- x -> fp16 ----------
__global__ void k_convx(const float* __restrict__ x) {
  size_t total4 = (size_t)BATCH * SEQ * ISZ / 4;
  for (size_t i = blockIdx.x * (size_t)blockDim.x + threadIdx.x; i < total4;
       i += (size_t)gridDim.x * blockDim.x) {
    float4 v = *(const float4*)(x + i * 4);
    __half2* dst = (__half2*)(g_x16 + i * 4);
    dst[0] = __floats2half2_rn(v.x, v.y);
    dst[1] = __floats2half2_rn(v.z, v.w);
  }
}

// ---------- weight prep ----------
__global__ void k_prep(const float* __restrict__ Wf, const float* __restrict__ Wfb,
                       const float* __restrict__ Wi, const float* __restrict__ Wib,
                       const float* __restrict__ Wo, const float* __restrict__ Wob,
                       const float* __restrict__ Wc, const float* __restrict__ Wcb) {
  int total = G4 * 1536;
  for (int idx = blockIdx.x * blockDim.x + threadIdx.x; idx < total;
       idx += gridDim.x * blockDim.x) {
    int col = idx / 1536, k = idx - (idx / 1536) * 1536;
    int gate = col >> 10, j = col & 1023;
    const float* Ws = (gate == 0) ? Wf : (gate == 1) ? Wi : (gate == 2) ? Wo : Wc;
    float v = Ws[(size_t)j * 1536 + k];
    if (k < ISZ) {
      g_Wx16[(size_t)col * ISZ + k] = __float2half(v);
    } else {
      int ct = j >> 3, u = j & 7, c = gate * 8 + u;
      g_Wh16[((size_t)ct * 32 + c) * HSZ + (k - ISZ)] = __float2half(v);
    }
    if (k == 0) {
      const float* Bs = (gate == 0) ? Wfb : (gate == 1) ? Wib : (gate == 2) ? Wob : Wcb;
      g_bias[col] = Bs[j];
    }
  }
}

// ---------- gx = x @ Wx^T + b : pipelined, 2 CTAs/SM, f32 output (champion) ----------
#define GXC 136
#define GX_STAGEH ((64 + 128) * GXC)
#define GX_SMEM (2 * GX_STAGEH * 2)
__global__ void __launch_bounds__(256, 2) k_gemmx() {
  extern __shared__ __half sm[];
  const int t = blockIdx.y, col0 = blockIdx.x * 128, tid = threadIdx.x;
  const int lane = tid & 31, w = tid >> 5, gid = lane >> 2, tig = lane & 3;
  const int rb = 32 * (w & 1), cb = 32 * (w >> 1);

  auto issue = [&](int c, int s) {
    __half* As = sm + s * GX_STAGEH;
    __half* Bs = As + 64 * GXC;
    #pragma unroll
    for (int it = 0; it < 4; ++it) {
      int u = it * 256 + tid, b = u >> 4, ko = (u & 15) * 8;
      cp16((uint32_t)__cvta_generic_to_shared(As + b * GXC + ko),
           g_x16 + ((size_t)b * SEQ + t) * ISZ + c * 128 + ko);
    }
    #pragma unroll
    for (int it = 0; it < 8; ++it) {
      int u = it * 256 + tid, cc = u >> 4, ko = (u & 15) * 8;
      cp16((uint32_t)__cvta_generic_to_shared(Bs + cc * GXC + ko),
           g_Wx16 + (size_t)(col0 + cc) * ISZ + c * 128 + ko);
    }
    cp_commit();
  };

  uint32_t a_ad[2], b_ad[2];
  {
    int row16 = lane & 15, koff = (lane >> 4) * 8;
    a_ad[0] = (uint32_t)__cvta_generic_to_shared(sm + (rb + row16) * GXC + koff);
    a_ad[1] = (uint32_t)__cvta_generic_to_shared(sm + (rb + 16 + row16) * GXC + koff);
    int j = lane >> 3, r = lane & 7;
    b_ad[0] = (uint32_t)__cvta_generic_to_shared(
        sm + 64 * GXC + (cb + (j >> 1) * 8 + r) * GXC + (j & 1) * 8);
    b_ad[1] = (uint32_t)__cvta_generic_to_shared(
        sm + 64 * GXC + (cb + 16 + (j >> 1) * 8 + r) * GXC + (j & 1) * 8);
  }

  float acc[2][4][4];
  #pragma unroll
  for (int m = 0; m < 2; m++)
    #pragma unroll
    for (int n = 0; n < 4; n++)
      #pragma unroll
      for (int q = 0; q < 4; q++) acc[m][n][q] = 0.f;

  issue(0, 0);
  #pragma unroll
  for (int c = 0; c < 4; ++c) {
    if (c < 3) { issue(c + 1, (c + 1) & 1); cp_wait<1>(); }
    else       { cp_wait<0>(); }
    __syncthreads();
    uint32_t so = (uint32_t)((c & 1) * GX_STAGEH * 2);
    #pragma unroll
    for (int kk = 0; kk < 8; ++kk) {
      uint32_t kb = so + kk * 32;
      uint32_t a[2][4], b[4][2];
      ldsm4(a[0][0], a[0][1], a[0][2], a[0][3], a_ad[0] + kb);
      ldsm4(a[1][0], a[1][1], a[1][2], a[1][3], a_ad[1] + kb);
      ldsm4(b[0][0], b[0][1], b[1][0], b[1][1], b_ad[0] + kb);
      ldsm4(b[2][0], b[2][1], b[3][0], b[3][1], b_ad[1] + kb);
      #pragma unroll
      for (int m = 0; m < 2; m++)
        #pragma unroll
        for (int n = 0; n < 4; n++)
          mma16816(acc[m][n], a[m][0], a[m][1], a[m][2], a[m][3], b[n][0], b[n][1]);
    }
    __syncthreads();
  }

  #pragma unroll
  for (int m = 0; m < 2; m++) {
    #pragma unroll
    for (int n = 0; n < 4; n++) {
      int row = rb + m * 16 + gid;
      int gcol = col0 + cb + n * 8 + tig * 2;
      int gate = gcol >> 10, j = gcol & 1023, ct = j >> 3, u = j & 7;
      int c = gate * 8 + u;
      float b0 = g_bias[gcol], b1 = g_bias[gcol + 1];
      size_t base = ((size_t)t * NCTA + ct) * (BATCH * 32);
      float* o0 = g_gx + base + (size_t)row * 32 + c;
      o0[0] = acc[m][n][0] + b0;  o0[1] = acc[m][n][1] + b1;
      float* o1 = g_gx + base + (size_t)(row + 8) * 32 + c;
      o1[0] = acc[m][n][2] + b0;  o1[1] = acc[m][n][3] + b1;
    }
  }
}

// ---------- persistent recurrence: TMA-staged h (no clusters) ----------
// SMEM: h 128KB (SW128 TMA) + Wh 64.5KB + gates 8.25KB + c 2KB + 4 mbar
#define OFF_H     0
#define OFF_W     131072
#define OFF_GATES (131072 + 66048)
#define OFF_C     (OFF_GATES + 8448)
#define OFF_MBAR  (OFF_C + 2048)
#define LSTM_SMEM (OFF_MBAR + 32)
__global__ void __launch_bounds__(256, 1)
k_lstm(const __grid_constant__ CUtensorMap tm0,
       const __grid_constant__ CUtensorMap tm1) {
  extern __shared__ char smraw[];
  __half* w_sm  = (__half*)(smraw + OFF_W);    // [32][1032]
  float*  gates = (float*)(smraw + OFF_GATES); // [64][33]
  float*  c_sm  = (float*)(smraw + OFF_C);     // [8][64] u*64+b

  const int tid = threadIdx.x, cta = blockIdx.x;
  const int lane = tid & 31, w = tid >> 5;
  const int gid = lane >> 2, tig = lane & 3;
  const int mblk = w & 3, n0 = (w >> 2) * 16;
  const uint32_t smem_base = (uint32_t)__cvta_generic_to_shared(smraw);
  const uint32_t h_smem = smem_base + OFF_H;
  const uint32_t mbar0  = smem_base + OFF_MBAR;

  // persistent Wh slice: 32 x 1024 halfs (64 KB)
  {
    const uint4* src = (const uint4*)(g_Wh16 + (size_t)cta * 32 * HSZ);
    #pragma unroll
    for (int it = 0; it < 16; ++it) {
      int i8 = (tid + it * 256) * 8, r = i8 >> 10, k = i8 & 1023;
      *(uint4*)(w_sm + r * 1032 + k) = src[tid + it * 256];
    }
  }
  for (int i = tid; i < 512; i += 256) c_sm[i] = 0.f;
  if (tid == 0) {
    #pragma unroll
    for (int c = 0; c < 4; ++c)
      asm volatile("mbarrier.init.shared.b64 [%0], 1;" :: "r"(mbar0 + c * 8) : "memory");
  }
  __syncthreads();

  // ldsm addressing for SW128 h tile: row = batch (128B), z = kc
  const int brow = mblk * 16 + (lane & 15);
  const uint32_t a_base = h_smem + (uint32_t)brow * 128;
  const uint32_t bx4 = (uint32_t)(brow & 7);
  const uint32_t ksel = (uint32_t)(lane >> 4);
  uint32_t b_ad;
  {
    int j = lane >> 3, r = lane & 7;
    b_ad = (uint32_t)__cvta_generic_to_shared(
        w_sm + (n0 + (j >> 1) * 8 + r) * 1032 + (j & 1) * 8);
  }

  const int pb = tid & 63, pu = (tid >> 6) * 2;

  for (int t = 0; t < SEQ; ++t) {
    int p = t & 1;

    // prefetch gx for this step (independent of the barrier)
    const float* gxp = g_gx + ((size_t)t * NCTA + cta) * (BATCH * 32) + pb * 32 + pu;
    float2 gf = *(const float2*)(gxp + 0);
    float2 gi = *(const float2*)(gxp + 8);
    float2 go = *(const float2*)(gxp + 16);
    float2 gg = *(const float2*)(gxp + 24);

    // wait for every CTA to finish step t-1 (acquire); this also orders all
    // of OUR step t-1 ldsm reads before the TMA re-write below (WAR guard)
    if (t > 0) {
      if (tid < NCTA) {
        while (ld_acq(&g_flag[tid]) < (unsigned)t) { }
      }
      __syncthreads();
    }

    // stage h via 4 chunked TMA loads (32 KB each), one mbarrier per chunk
    if (tid == 0) {
      asm volatile("fence.proxy.async;" ::: "memory");
      const CUtensorMap* tmp = p ? &tm1 : &tm0;
      #pragma unroll
      for (int c = 0; c < 4; ++c) {
        uint32_t mb = mbar0 + c * 8;
        asm volatile("mbarrier.arrive.expect_tx.shared.b64 _, [%0], %1;"
                     :: "r"(mb), "r"(32768u) : "memory");
        asm volatile(
          "cp.async.bulk.tensor.3d.shared::cta.global.tile"
          ".mbarrier::complete_tx::bytes "
          "[%0], [%1, {%2, %3, %4}], [%5];"
          :: "r"(h_smem + (uint32_t)c * 32768u), "l"(tmp),
             "r"(0), "r"(0), "r"(c * 4), "r"(mb)
          : "memory");
      }
    }

    float acc[2][4];
    #pragma unroll
    for (int n = 0; n < 2; n++)
      #pragma unroll
      for (int q = 0; q < 4; q++) acc[n][q] = 0.f;

    // MMA ladder: wait each chunk's mbarrier (all threads), then 16 kk iters
    #pragma unroll
    for (int c = 0; c < 4; ++c) {
      mbar_wait(mbar0 + c * 8, (uint32_t)(t & 1));
      #pragma unroll
      for (int kk = 0; kk < 16; ++kk) {
        const int k0 = (c * 16 + kk) * 16;
        uint32_t u0 = (uint32_t)((k0 >> 3) & 6) + ksel;
        uint32_t a_ad = a_base + (uint32_t)((k0 >> 6) << 13) + ((u0 ^ bx4) << 4);
        uint32_t a0, a1, a2, a3, b00, b01, b10, b11;
        ldsm4(a0, a1, a2, a3, a_ad);
        ldsm4(b00, b01, b10, b11, b_ad + (uint32_t)(k0 * 2));
        mma16816(acc[0], a0, a1, a2, a3, b00, b01);
        mma16816(acc[1], a0, a1, a2, a3, b10, b11);
      }
    }

    // exchange gate partials via SMEM (each warp owns 16 of the 32 cols)
    #pragma unroll
    for (int hh = 0; hh < 2; ++hh) {
      int r = mblk * 16 + gid + hh * 8;
      gates[r * 33 + n0 + 2 * tig]         = acc[0][hh * 2 + 0];
      gates[r * 33 + n0 + 2 * tig + 1]     = acc[0][hh * 2 + 1];
      gates[r * 33 + n0 + 8 + 2 * tig]     = acc[1][hh * 2 + 0];
      gates[r * 33 + n0 + 8 + 2 * tig + 1] = acc[1][hh * 2 + 1];
    }
    __syncthreads();

    // fused pointwise LSTM update: thread handles (pb, pu) and (pb, pu+1)
    float hv[2];
    #pragma unroll
    for (int q = 0; q < 2; ++q) {
      int u = pu + q;
      float fg = fsig(gates[pb * 33 + u]       + (q ? gf.y : gf.x));
      float ig = fsig(gates[pb * 33 + 8 + u]   + (q ? gi.y : gi.x));
      float og = fsig(gates[pb * 33 + 16 + u]  + (q ? go.y : go.x));
      float cg = ftanh(gates[pb * 33 + 24 + u] + (q ? gg.y : gg.x));
      float cn = fg * c_sm[u * 64 + pb] + ig * cg;
      c_sm[u * 64 + pb] = cn;
      hv[q] = og * ftanh(cn);
    }
    // h store in TMA layout [kc][b][64]: col = (cta&7)*8+pu, kc = cta>>3
    {
      size_t ho = ((size_t)(cta >> 3) * 64 + pb) * 64 + (cta & 7) * 8 + pu;
      *(__half2*)(g_hbuf[p ^ 1] + ho) = __floats2half2_rn(hv[0], hv[1]);
    }
    if (t == SEQ - 1) {
      int gu = cta * 8 + pu;
      *(float2*)(g_hT + pb * HSZ + gu) = make_float2(hv[0], hv[1]);
    }

    // publish (release); CTA barrier + release-store carry visibility
    __syncthreads();
    if (tid == 0) st_rel(&g_flag[cta], (unsigned)(t + 1));
  }
}

// ---------- logits ----------
__global__ void k_logits(const float* __restrict__ ow, const float* __restrict__ ob,
                         float* __restrict__ out) {
  int b = blockIdx.x, tid = threadIdx.x, o = tid >> 5, lane = tid & 31;
  if (o >= 10) return;
  float s = 0.f;
  for (int k = lane; k < HSZ; k += 32) s += g_hT[b * HSZ + k] * ow[o * HSZ + k];
  #pragma unroll
  for (int d = 16; d > 0; d >>= 1) s += __shfl_down_sync(0xFFFFFFFF, s, d);
  if (lane == 0) out[b * 10 + o] = s + ob[o];
}

// ---------- host ----------
typedef CUresult (*EncodeFn)(CUtensorMap*, CUtensorMapDataType, cuuint32_t, void*,
                             const cuuint64_t*, const cuuint64_t*, const cuuint32_t*,
                             const cuuint32_t*, CUtensorMapInterleave, CUtensorMapSwizzle,
                             CUtensorMapL2promotion, CUtensorMapFloatOOBfill);

static void make_tm(CUtensorMap* tm, void* base) {
  void* fp = nullptr;
  cudaDriverEntryPointQueryResult qr;
  cudaGetDriverEntryPoint("cuTensorMapEncodeTiled", &fp, cudaEnableDefault, &qr);
  EncodeFn fn = (EncodeFn)fp;
  cuuint64_t dims[3]    = {128, 64, 16};      // bytes-in-row, batch, kc
  cuuint64_t strides[2] = {128, 128 * 64};
  cuuint32_t box[3]     = {128, 64, 4};       // 32 KB chunk
  cuuint32_t es[3]      = {1, 1, 1};
  fn(tm, CU_TENSOR_MAP_DATA_TYPE_UINT8, 3, base, dims, strides, box, es,
     CU_TENSOR_MAP_INTERLEAVE_NONE, CU_TENSOR_MAP_SWIZZLE_128B,
     CU_TENSOR_MAP_L2_PROMOTION_L2_128B, CU_TENSOR_MAP_FLOAT_OOB_FILL_NONE);
}

extern "C" void kernel_launch(void* const* d_in, const int* in_sizes, int n_in,
                              void* d_out, int out_size) {
  const float* x   = (const float*)d_in[0];
  const float* Wf  = (const float*)d_in[1];  const float* Wfb = (const float*)d_in[2];
  const float* Wi  = (const float*)d_in[3];  const float* Wib = (const float*)d_in[4];
  const float* Wo  = (const float*)d_in[5];  const float* Wob = (const float*)d_in[6];
  const float* Wc  = (const float*)d_in[7];  const float* Wcb = (const float*)d_in[8];
  const float* ow  = (const float*)d_in[9];  const float* ob  = (const float*)d_in[10];
  float* out = (float*)d_out;

  void* hbase = nullptr;
  cudaGetSymbolAddress(&hbase, g_hbuf);
  CUtensorMap tm0, tm1;
  make_tm(&tm0, hbase);
  make_tm(&tm1, (char*)hbase + 16 * 64 * 64 * 2);

  cudaFuncSetAttribute(k_gemmx, cudaFuncAttributeMaxDynamicSharedMemorySize, GX_SMEM);
  cudaFuncSetAttribute(k_lstm,  cudaFuncAttributeMaxDynamicSharedMemorySize, LSTM_SMEM);

  k_init<<<256, 256>>>();
  k_convx<<<4096, 256>>>(x);
  k_prep<<<8192, 256>>>(Wf, Wfb, Wi, Wib, Wo, Wob, Wc, Wcb);
  k_gemmx<<<dim3(32, SEQ), 256, GX_SMEM>>>();
  k_lstm<<<NCTA, 256, LSTM_SMEM>>>(tm0, tm1);
  k_logits<<<BATCH, 320>>>(ow, ob, out);
}